// round 12
// baseline (speedup 1.0000x reference)
#include <cuda_runtime.h>
#include <cuda_bf16.h>
#include <cstdint>
#include <math.h>

// Problem dims (fixed by dataset): B=1024, I=512, O=512.
#define B_DIM 1024
#define I_DIM 512
#define O_DIM 512

#define TM 64
#define TN 64
#define KC 64                 // k per smem stage
#define NCH (I_DIM / KC)      // 8
#define NSTAGE 3

typedef __nv_bfloat16 bf16;

// ---------------- device scratch (allocation-free) ----------------
__device__ __align__(16) bf16  g_xhi[B_DIM * I_DIM];
__device__ __align__(16) bf16  g_xlo[B_DIM * I_DIM];
__device__ __align__(16) bf16  g_x2 [B_DIM * I_DIM];
__device__ __align__(16) bf16  g_whi[O_DIM * I_DIM];
__device__ __align__(16) bf16  g_wlo[O_DIM * I_DIM];
__device__ __align__(16) bf16  g_s2 [O_DIM * I_DIM];   // v^2 + eps
__device__ __align__(16) bf16  g_nc2[O_DIM * I_DIM];   // -2 c (v^2+eps)
__device__ __align__(16) float g_eK [O_DIM];           // exp(-sum c^2 (v^2+eps))

// ---------------- helpers ----------------
__device__ __forceinline__ unsigned pk2(float a, float b) {
    __nv_bfloat162 t;
    t.x = __float2bfloat16_rn(a);
    t.y = __float2bfloat16_rn(b);
    return *(unsigned*)&t;
}
__device__ __forceinline__ uint32_t smem_u32(const void* p) {
    uint32_t a;
    asm("{ .reg .u64 t; cvta.to.shared.u64 t, %1; cvt.u32.u64 %0, t; }" : "=r"(a) : "l"(p));
    return a;
}
__device__ __forceinline__ void cpa16(uint32_t dst, const void* src) {
    asm volatile("cp.async.cg.shared.global [%0], [%1], 16;" :: "r"(dst), "l"(src));
}
#define CP_COMMIT()  asm volatile("cp.async.commit_group;" ::: "memory")
#define CP_WAIT(n)   asm volatile("cp.async.wait_group %0;" :: "n"(n) : "memory")

#define LDMX4(r, addr)                                                        \
    asm volatile("ldmatrix.sync.aligned.m8n8.x4.shared.b16 {%0,%1,%2,%3}, [%4];" \
        : "=r"((r)[0]), "=r"((r)[1]), "=r"((r)[2]), "=r"((r)[3]) : "r"(addr))

__device__ __forceinline__ void mma16816(float* c, const uint32_t* a,
                                         uint32_t b0, uint32_t b1) {
    asm volatile(
        "mma.sync.aligned.m16n8k16.row.col.f32.bf16.bf16.f32 "
        "{%0,%1,%2,%3},{%4,%5,%6,%7},{%8,%9},{%0,%1,%2,%3};"
        : "+f"(c[0]), "+f"(c[1]), "+f"(c[2]), "+f"(c[3])
        : "r"(a[0]), "r"(a[1]), "r"(a[2]), "r"(a[3]), "r"(b0), "r"(b1));
}

// ---------------- fused prep kernel (one launch) ----------------
__global__ void prep_all_kernel(const float* __restrict__ X,
                                const float* __restrict__ W,
                                const float* __restrict__ C,
                                const float* __restrict__ V)
{
    const int blk = blockIdx.x;
    const int tid = threadIdx.x;

    if (blk < 512) {
        int i = blk * 256 + tid;
        float4 x = ((const float4*)X)[i];
        float h0 = __bfloat162float(__float2bfloat16_rn(x.x));
        float h1 = __bfloat162float(__float2bfloat16_rn(x.y));
        float h2 = __bfloat162float(__float2bfloat16_rn(x.z));
        float h3 = __bfloat162float(__float2bfloat16_rn(x.w));
        ((uint2*)g_xhi)[i] = make_uint2(pk2(x.x, x.y), pk2(x.z, x.w));
        ((uint2*)g_xlo)[i] = make_uint2(pk2(x.x - h0, x.y - h1), pk2(x.z - h2, x.w - h3));
        ((uint2*)g_x2 )[i] = make_uint2(pk2(x.x * x.x, x.y * x.y), pk2(x.z * x.z, x.w * x.w));
    } else if (blk < 768) {
        int i = (blk - 512) * 256 + tid;
        float4 w = ((const float4*)W)[i];
        float h0 = __bfloat162float(__float2bfloat16_rn(w.x));
        float h1 = __bfloat162float(__float2bfloat16_rn(w.y));
        float h2 = __bfloat162float(__float2bfloat16_rn(w.z));
        float h3 = __bfloat162float(__float2bfloat16_rn(w.w));
        ((uint2*)g_whi)[i] = make_uint2(pk2(w.x, w.y), pk2(w.z, w.w));
        ((uint2*)g_wlo)[i] = make_uint2(pk2(w.x - h0, w.y - h1), pk2(w.z - h2, w.w - h3));
    } else {
        __shared__ float red[2][4];
        const int g = tid >> 7;
        const int t = tid & 127;
        const int o = (blk - 768) * 2 + g;
        float4 c = ((const float4*)(C + (size_t)o * I_DIM))[t];
        float4 v = ((const float4*)(V + (size_t)o * I_DIM))[t];
        float s0 = v.x * v.x + 1e-32f, s1 = v.y * v.y + 1e-32f;
        float s2 = v.z * v.z + 1e-32f, s3 = v.w * v.w + 1e-32f;
        float ks = c.x * c.x * s0 + c.y * c.y * s1 + c.z * c.z * s2 + c.w * c.w * s3;
        ((uint2*)(g_s2  + (size_t)o * I_DIM))[t] =
            make_uint2(pk2(s0, s1), pk2(s2, s3));
        ((uint2*)(g_nc2 + (size_t)o * I_DIM))[t] =
            make_uint2(pk2(-2.0f * c.x * s0, -2.0f * c.y * s1),
                       pk2(-2.0f * c.z * s2, -2.0f * c.w * s3));
        #pragma unroll
        for (int d = 16; d > 0; d >>= 1) ks += __shfl_xor_sync(0xffffffffu, ks, d);
        if ((t & 31) == 0) red[g][(t >> 5) & 3] = ks;
        __syncthreads();
        if (t == 0) g_eK[o] = expf(-(red[g][0] + red[g][1] + red[g][2] + red[g][3]));
    }
}

// ---------------- main mma.sync kernel ----------------
// Stage layout: 7 bf16 tiles of [64 rows][64 k] = 8 KB each, XOR-swizzled.
#define T_XHI 0
#define T_XLO 8192
#define T_X2  16384
#define T_WHI 24576
#define T_WLO 32768
#define T_S2  40960
#define T_NC2 49152
#define STAGE_BYTES 57344
#define SMEM_TOTAL  (NSTAGE * STAGE_BYTES)   // 168 KB -> 1 CTA/SM

__device__ __forceinline__ uint32_t sw_off(int row, int c16) {
    return (uint32_t)(row * 128 + (((c16) ^ (row & 7)) << 4));
}

// per-ks register fragments (A: 32 m rows x 3 matrices; B: 16 n cols x 4)
struct Frag {
    uint32_t axh[2][4], axl[2][4], ax2[2][4];
    uint32_t bwh[4], bwl[4], bs2[4], bnc[4];
};

__global__ __launch_bounds__(256, 1)
void fgn_mma_kernel(const float* __restrict__ bias, float* __restrict__ out) {
    extern __shared__ char smem[];
    const uint32_t sb = smem_u32(smem);
    const int tid  = threadIdx.x;
    const int lane = tid & 31;
    const int wid  = tid >> 5;          // 0..7
    const int wm   = wid >> 2;          // 0..1 : m offset 32*wm
    const int wn   = wid & 3;           // 0..3 : n offset 16*wn
    const int m0   = blockIdx.y * TM;
    const int n0   = blockIdx.x * TN;

    // staging: each tile has 64 rows x 8 c16 = 512 slots; 2 per thread
    const int srow = tid >> 3;
    const int sc   = tid & 7;

    auto load_chunk = [&](int stage, int ch) {
        const uint32_t base = sb + stage * STAGE_BYTES;
        const size_t k0 = (size_t)ch * KC + sc * 8;
        #pragma unroll
        for (int j = 0; j < 2; j++) {
            const int row = srow + 32 * j;
            const uint32_t so = sw_off(row, sc);
            const size_t am = (size_t)(m0 + row) * I_DIM + k0;
            const size_t bn = (size_t)(n0 + row) * I_DIM + k0;
            cpa16(base + T_XHI + so, g_xhi + am);
            cpa16(base + T_XLO + so, g_xlo + am);
            cpa16(base + T_X2  + so, g_x2  + am);
            cpa16(base + T_WHI + so, g_whi + bn);
            cpa16(base + T_WLO + so, g_wlo + bn);
            cpa16(base + T_S2  + so, g_s2  + bn);
            cpa16(base + T_NC2 + so, g_nc2 + bn);
        }
    };

    // 5 independent accumulator sets: NO intra-ks RAW chains.
    float aL1[2][2][4] = {};   // xhi * whi
    float aL2[2][2][4] = {};   // xhi * wlo
    float aL3[2][2][4] = {};   // xlo * whi
    float aG1[2][2][4] = {};   // x2  * s2
    float aG2[2][2][4] = {};   // xhi * nc2

    const int lr = lane & 15;
    const int lc = lane >> 4;

    auto frag_load = [&](Frag& f, uint32_t base, int ks) {
        const int c16 = 2 * ks + lc;
        #pragma unroll
        for (int mt = 0; mt < 2; mt++) {
            uint32_t ad = base + sw_off(wm * 32 + mt * 16 + lr, c16);
            LDMX4(f.axh[mt], ad + T_XHI);
            LDMX4(f.axl[mt], ad + T_XLO);
            LDMX4(f.ax2[mt], ad + T_X2);
        }
        uint32_t bd = base + sw_off(wn * 16 + lr, c16);
        LDMX4(f.bwh, bd + T_WHI);
        LDMX4(f.bwl, bd + T_WLO);
        LDMX4(f.bs2, bd + T_S2);
        LDMX4(f.bnc, bd + T_NC2);
    };
    auto frag_mma = [&](const Frag& f) {
        #pragma unroll
        for (int mt = 0; mt < 2; mt++)
            #pragma unroll
            for (int nt = 0; nt < 2; nt++) {
                mma16816(aL1[mt][nt], f.axh[mt], f.bwh[nt], f.bwh[nt + 2]);
                mma16816(aL2[mt][nt], f.axh[mt], f.bwl[nt], f.bwl[nt + 2]);
                mma16816(aL3[mt][nt], f.axl[mt], f.bwh[nt], f.bwh[nt + 2]);
                mma16816(aG1[mt][nt], f.ax2[mt], f.bs2[nt], f.bs2[nt + 2]);
                mma16816(aG2[mt][nt], f.axh[mt], f.bnc[nt], f.bnc[nt + 2]);
            }
    };

    // -------- prologue: fill 2 of 3 stages --------
    load_chunk(0, 0); CP_COMMIT();
    load_chunk(1, 1); CP_COMMIT();

    Frag fr[2];
    #pragma unroll 1
    for (int i = 0; i < NCH; i++) {
        CP_WAIT(1);
        __syncthreads();
        if (i + 2 < NCH) {
            load_chunk((i + 2) % NSTAGE, i + 2);
            CP_COMMIT();
        }
        const uint32_t base = sb + (i % NSTAGE) * STAGE_BYTES;
        frag_load(fr[0], base, 0);
        #pragma unroll
        for (int ks = 0; ks < KC / 16; ks++) {
            if (ks + 1 < KC / 16) frag_load(fr[(ks + 1) & 1], base, ks + 1);
            frag_mma(fr[ks & 1]);
        }
    }

    // -------- epilogue: fold accumulators; out = (L+b)*ek*exp(-G) --------
    const int gq = lane >> 2;
    const int tg = lane & 3;
    #pragma unroll
    for (int mt = 0; mt < 2; mt++)
        #pragma unroll
        for (int nt = 0; nt < 2; nt++) {
            int gn = n0 + wn * 16 + nt * 8 + 2 * tg;
            float b0 = bias[gn],  b1 = bias[gn + 1];
            float e0 = g_eK[gn],  e1 = g_eK[gn + 1];
            int mlo = m0 + wm * 32 + mt * 16 + gq;
            float L0 = aL1[mt][nt][0] + aL2[mt][nt][0] + aL3[mt][nt][0];
            float L1 = aL1[mt][nt][1] + aL2[mt][nt][1] + aL3[mt][nt][1];
            float L2 = aL1[mt][nt][2] + aL2[mt][nt][2] + aL3[mt][nt][2];
            float L3 = aL1[mt][nt][3] + aL2[mt][nt][3] + aL3[mt][nt][3];
            float G0 = aG1[mt][nt][0] + aG2[mt][nt][0];
            float G1 = aG1[mt][nt][1] + aG2[mt][nt][1];
            float G2 = aG1[mt][nt][2] + aG2[mt][nt][2];
            float G3 = aG1[mt][nt][3] + aG2[mt][nt][3];
            float2 o0 = make_float2((L0 + b0) * e0 * expf(-G0),
                                    (L1 + b1) * e1 * expf(-G1));
            *(float2*)&out[(size_t)mlo * O_DIM + gn] = o0;
            float2 o1 = make_float2((L2 + b0) * e0 * expf(-G2),
                                    (L3 + b1) * e1 * expf(-G3));
            *(float2*)&out[(size_t)(mlo + 8) * O_DIM + gn] = o1;
        }
}

// ---------------- launch ----------------
extern "C" void kernel_launch(void* const* d_in, const int* in_sizes, int n_in,
                              void* d_out, int out_size)
{
    const float* X    = (const float*)d_in[0];
    const float* W    = (const float*)d_in[1];
    const float* bias = (const float*)d_in[2];
    const float* C    = (const float*)d_in[3];
    const float* V    = (const float*)d_in[4];
    (void)in_sizes; (void)n_in; (void)out_size;

    cudaFuncSetAttribute(fgn_mma_kernel,
                         cudaFuncAttributeMaxDynamicSharedMemorySize, SMEM_TOTAL);

    prep_all_kernel<<<1024, 256>>>(X, W, C, V);

    dim3 grid(O_DIM / TN, B_DIM / TM);   // 8 x 16 = 128 CTAs
    fgn_mma_kernel<<<grid, 256, SMEM_TOTAL>>>(bias, (float*)d_out);
}

// round 13
// speedup vs baseline: 1.1382x; 1.1382x over previous
#include <cuda_runtime.h>
#include <cuda_fp16.h>
#include <cstdint>
#include <math.h>

// Problem dims (fixed by dataset): B=1024, I=512, O=512.
#define B_DIM 1024
#define I_DIM 512
#define O_DIM 512

#define TM 64
#define TN 64
#define KC 64                 // k per smem stage
#define NCH (I_DIM / KC)      // 8
#define NSTAGE 3

#define SC   65536.0f         // fp16 range lift for s2/nc2 (2^16)
#define ISC  (1.0f / 65536.0f)

// ---------------- device scratch (allocation-free) ----------------
__device__ __align__(16) __half g_xh [B_DIM * I_DIM];  // rn(x)
__device__ __align__(16) __half g_x2 [B_DIM * I_DIM];  // rn(x^2)
__device__ __align__(16) __half g_wh [O_DIM * I_DIM];  // rn(w)
__device__ __align__(16) __half g_s2 [O_DIM * I_DIM];  // rn((v^2+eps)*2^16)
__device__ __align__(16) __half g_nc2[O_DIM * I_DIM];  // rn(-2 c (v^2+eps)*2^16)
__device__ __align__(16) float  g_eK [O_DIM];          // exp(-sum c^2 (v^2+eps))

// ---------------- helpers ----------------
__device__ __forceinline__ unsigned pkh2(float a, float b) {
    __half2 t = __halves2half2(__float2half_rn(a), __float2half_rn(b));
    return *(unsigned*)&t;
}
__device__ __forceinline__ uint32_t smem_u32(const void* p) {
    uint32_t a;
    asm("{ .reg .u64 t; cvta.to.shared.u64 t, %1; cvt.u32.u64 %0, t; }" : "=r"(a) : "l"(p));
    return a;
}
__device__ __forceinline__ void cpa16(uint32_t dst, const void* src) {
    asm volatile("cp.async.cg.shared.global [%0], [%1], 16;" :: "r"(dst), "l"(src));
}
#define CP_COMMIT()  asm volatile("cp.async.commit_group;" ::: "memory")
#define CP_WAIT(n)   asm volatile("cp.async.wait_group %0;" :: "n"(n) : "memory")

#define LDMX4(r, addr)                                                        \
    asm volatile("ldmatrix.sync.aligned.m8n8.x4.shared.b16 {%0,%1,%2,%3}, [%4];" \
        : "=r"((r)[0]), "=r"((r)[1]), "=r"((r)[2]), "=r"((r)[3]) : "r"(addr))

__device__ __forceinline__ void mma16816(float* c, const uint32_t* a,
                                         uint32_t b0, uint32_t b1) {
    asm volatile(
        "mma.sync.aligned.m16n8k16.row.col.f32.f16.f16.f32 "
        "{%0,%1,%2,%3},{%4,%5,%6,%7},{%8,%9},{%0,%1,%2,%3};"
        : "+f"(c[0]), "+f"(c[1]), "+f"(c[2]), "+f"(c[3])
        : "r"(a[0]), "r"(a[1]), "r"(a[2]), "r"(a[3]), "r"(b0), "r"(b1));
}

// ---------------- fused prep kernel (one launch) ----------------
// blocks [0,512)    : x -> xh, x2         (fp16)
// blocks [512,768)  : w -> wh             (fp16)
// blocks [768,1024) : s2', nc2', eK ; 2 output-rows per block
__global__ void prep_all_kernel(const float* __restrict__ X,
                                const float* __restrict__ W,
                                const float* __restrict__ C,
                                const float* __restrict__ V)
{
    const int blk = blockIdx.x;
    const int tid = threadIdx.x;

    if (blk < 512) {
        int i = blk * 256 + tid;
        float4 x = ((const float4*)X)[i];
        ((uint2*)g_xh)[i] = make_uint2(pkh2(x.x, x.y), pkh2(x.z, x.w));
        ((uint2*)g_x2)[i] = make_uint2(pkh2(x.x * x.x, x.y * x.y),
                                       pkh2(x.z * x.z, x.w * x.w));
    } else if (blk < 768) {
        int i = (blk - 512) * 256 + tid;
        float4 w = ((const float4*)W)[i];
        ((uint2*)g_wh)[i] = make_uint2(pkh2(w.x, w.y), pkh2(w.z, w.w));
    } else {
        __shared__ float red[2][4];
        const int g = tid >> 7;
        const int t = tid & 127;
        const int o = (blk - 768) * 2 + g;
        float4 c = ((const float4*)(C + (size_t)o * I_DIM))[t];
        float4 v = ((const float4*)(V + (size_t)o * I_DIM))[t];
        float s0 = v.x * v.x + 1e-32f, s1 = v.y * v.y + 1e-32f;
        float s2 = v.z * v.z + 1e-32f, s3 = v.w * v.w + 1e-32f;
        float ks = c.x * c.x * s0 + c.y * c.y * s1 + c.z * c.z * s2 + c.w * c.w * s3;
        ((uint2*)(g_s2  + (size_t)o * I_DIM))[t] =
            make_uint2(pkh2(s0 * SC, s1 * SC), pkh2(s2 * SC, s3 * SC));
        ((uint2*)(g_nc2 + (size_t)o * I_DIM))[t] =
            make_uint2(pkh2(-2.0f * c.x * s0 * SC, -2.0f * c.y * s1 * SC),
                       pkh2(-2.0f * c.z * s2 * SC, -2.0f * c.w * s3 * SC));
        #pragma unroll
        for (int d = 16; d > 0; d >>= 1) ks += __shfl_xor_sync(0xffffffffu, ks, d);
        if ((t & 31) == 0) red[g][(t >> 5) & 3] = ks;
        __syncthreads();
        if (t == 0) g_eK[o] = expf(-(red[g][0] + red[g][1] + red[g][2] + red[g][3]));
    }
}

// ---------------- main mma.sync kernel ----------------
// Stage layout: 5 fp16 tiles of [64 rows][64 k] = 8 KB each, XOR-swizzled.
#define T_XH  0
#define T_X2  8192
#define T_WH  16384
#define T_S2  24576
#define T_NC2 32768
#define STAGE_BYTES 40960
#define SMEM_TOTAL  (NSTAGE * STAGE_BYTES)   // 120 KB -> 1 CTA/SM

__device__ __forceinline__ uint32_t sw_off(int row, int c16) {
    return (uint32_t)(row * 128 + (((c16) ^ (row & 7)) << 4));
}

// per-ks register fragments
struct Frag {
    uint32_t axh[2][4], ax2[2][4];
    uint32_t bwh[4], bs2[4], bnc[4];
};

__global__ __launch_bounds__(256, 1)
void fgn_mma_kernel(const float* __restrict__ bias, float* __restrict__ out) {
    extern __shared__ char smem[];
    const uint32_t sb = smem_u32(smem);
    const int tid  = threadIdx.x;
    const int lane = tid & 31;
    const int wid  = tid >> 5;          // 0..7
    const int wm   = wid >> 2;          // 0..1 : m offset 32*wm
    const int wn   = wid & 3;           // 0..3 : n offset 16*wn
    const int m0   = blockIdx.y * TM;
    const int n0   = blockIdx.x * TN;

    // staging: each tile has 64 rows x 8 c16 = 512 slots; 2 per thread
    const int srow = tid >> 3;
    const int sc   = tid & 7;

    auto load_chunk = [&](int stage, int ch) {
        const uint32_t base = sb + stage * STAGE_BYTES;
        const size_t k0 = (size_t)ch * KC + sc * 8;
        #pragma unroll
        for (int j = 0; j < 2; j++) {
            const int row = srow + 32 * j;
            const uint32_t so = sw_off(row, sc);
            const size_t am = (size_t)(m0 + row) * I_DIM + k0;
            const size_t bn = (size_t)(n0 + row) * I_DIM + k0;
            cpa16(base + T_XH  + so, g_xh  + am);
            cpa16(base + T_X2  + so, g_x2  + am);
            cpa16(base + T_WH  + so, g_wh  + bn);
            cpa16(base + T_S2  + so, g_s2  + bn);
            cpa16(base + T_NC2 + so, g_nc2 + bn);
        }
    };

    // 3 independent accumulator sets
    float aL [2][2][4] = {};   // xh * wh
    float aG1[2][2][4] = {};   // x2 * s2'
    float aG2[2][2][4] = {};   // xh * nc2'

    const int lr = lane & 15;
    const int lc = lane >> 4;

    auto frag_load = [&](Frag& f, uint32_t base, int ks) {
        const int c16 = 2 * ks + lc;
        #pragma unroll
        for (int mt = 0; mt < 2; mt++) {
            uint32_t ad = base + sw_off(wm * 32 + mt * 16 + lr, c16);
            LDMX4(f.axh[mt], ad + T_XH);
            LDMX4(f.ax2[mt], ad + T_X2);
        }
        uint32_t bd = base + sw_off(wn * 16 + lr, c16);
        LDMX4(f.bwh, bd + T_WH);
        LDMX4(f.bs2, bd + T_S2);
        LDMX4(f.bnc, bd + T_NC2);
    };
    auto frag_mma = [&](const Frag& f) {
        #pragma unroll
        for (int mt = 0; mt < 2; mt++)
            #pragma unroll
            for (int nt = 0; nt < 2; nt++) {
                mma16816(aL [mt][nt], f.axh[mt], f.bwh[nt], f.bwh[nt + 2]);
                mma16816(aG1[mt][nt], f.ax2[mt], f.bs2[nt], f.bs2[nt + 2]);
                mma16816(aG2[mt][nt], f.axh[mt], f.bnc[nt], f.bnc[nt + 2]);
            }
    };

    // -------- prologue: fill 2 of 3 stages --------
    load_chunk(0, 0); CP_COMMIT();
    load_chunk(1, 1); CP_COMMIT();

    Frag fr[2];
    #pragma unroll 1
    for (int i = 0; i < NCH; i++) {
        CP_WAIT(1);
        __syncthreads();
        if (i + 2 < NCH) {
            load_chunk((i + 2) % NSTAGE, i + 2);
            CP_COMMIT();
        }
        const uint32_t base = sb + (i % NSTAGE) * STAGE_BYTES;
        frag_load(fr[0], base, 0);
        #pragma unroll
        for (int ks = 0; ks < KC / 16; ks++) {
            if (ks + 1 < KC / 16) frag_load(fr[(ks + 1) & 1], base, ks + 1);
            frag_mma(fr[ks & 1]);
        }
    }

    // -------- epilogue: out = (L + bias) * eK * exp(-(G1+G2)*2^-16) --------
    const int gq = lane >> 2;
    const int tg = lane & 3;
    #pragma unroll
    for (int mt = 0; mt < 2; mt++)
        #pragma unroll
        for (int nt = 0; nt < 2; nt++) {
            int gn = n0 + wn * 16 + nt * 8 + 2 * tg;
            float b0 = bias[gn],  b1 = bias[gn + 1];
            float e0 = g_eK[gn],  e1 = g_eK[gn + 1];
            int mlo = m0 + wm * 32 + mt * 16 + gq;
            float G0 = (aG1[mt][nt][0] + aG2[mt][nt][0]) * ISC;
            float G1 = (aG1[mt][nt][1] + aG2[mt][nt][1]) * ISC;
            float G2 = (aG1[mt][nt][2] + aG2[mt][nt][2]) * ISC;
            float G3 = (aG1[mt][nt][3] + aG2[mt][nt][3]) * ISC;
            float2 o0 = make_float2((aL[mt][nt][0] + b0) * e0 * expf(-G0),
                                    (aL[mt][nt][1] + b1) * e1 * expf(-G1));
            *(float2*)&out[(size_t)mlo * O_DIM + gn] = o0;
            float2 o1 = make_float2((aL[mt][nt][2] + b0) * e0 * expf(-G2),
                                    (aL[mt][nt][3] + b1) * e1 * expf(-G3));
            *(float2*)&out[(size_t)(mlo + 8) * O_DIM + gn] = o1;
        }
}

// ---------------- launch ----------------
extern "C" void kernel_launch(void* const* d_in, const int* in_sizes, int n_in,
                              void* d_out, int out_size)
{
    const float* X    = (const float*)d_in[0];
    const float* W    = (const float*)d_in[1];
    const float* bias = (const float*)d_in[2];
    const float* C    = (const float*)d_in[3];
    const float* V    = (const float*)d_in[4];
    (void)in_sizes; (void)n_in; (void)out_size;

    cudaFuncSetAttribute(fgn_mma_kernel,
                         cudaFuncAttributeMaxDynamicSharedMemorySize, SMEM_TOTAL);

    prep_all_kernel<<<1024, 256>>>(X, W, C, V);

    dim3 grid(O_DIM / TN, B_DIM / TM);   // 8 x 16 = 128 CTAs
    fgn_mma_kernel<<<grid, 256, SMEM_TOTAL>>>(bias, (float*)d_out);
}